// round 14
// baseline (speedup 1.0000x reference)
#include <cuda_runtime.h>
#include <cuda_bf16.h>
#include <math.h>

#define BTOT  16384
#define DHID  2048
#define RDIM  512
#define BHALF 8192
#define SHIFTC 10.0f

typedef unsigned int u32;

// ---------------- scratch (static device globals; no allocs) ----------------
__device__ __align__(16) __nv_bfloat16 g_hHi[(size_t)BTOT * DHID];
__device__ __align__(16) __nv_bfloat16 g_hLo[(size_t)BTOT * DHID];
__device__ __align__(16) __nv_bfloat16 g_wHi[(size_t)RDIM * DHID];
__device__ __align__(16) __nv_bfloat16 g_wLo[(size_t)RDIM * DHID];
__device__ __align__(16) __nv_bfloat16 g_Phi[(size_t)BTOT * RDIM];
__device__ __align__(16) __nv_bfloat16 g_Plo[(size_t)BTOT * RDIM];
__device__ float g_invn[BTOT];
__device__ float g_sumexp[BHALF];
__device__ float g_rowsum[BHALF];
__device__ float g_diag[BHALF];

// ---------------- baseline-PTX helpers ----------------
__device__ __forceinline__ u32 smem_u32(const void* p) {
    u32 a;
    asm("{ .reg .u64 t; cvta.to.shared.u64 t, %1; cvt.u32.u64 %0, t; }" : "=r"(a) : "l"(p));
    return a;
}
__device__ __forceinline__ void cp16(u32 dst, const void* src) {
    asm volatile("cp.async.cg.shared.global [%0], [%1], 16;" :: "r"(dst), "l"(src));
}
__device__ __forceinline__ void cp_commit() {
    asm volatile("cp.async.commit_group;" ::: "memory");
}
template <int N> __device__ __forceinline__ void cp_wait() {
    asm volatile("cp.async.wait_group %0;" :: "n"(N) : "memory");
}
__device__ __forceinline__ void ldm4(u32 a, u32& r0, u32& r1, u32& r2, u32& r3) {
    asm volatile("ldmatrix.sync.aligned.m8n8.x4.shared.b16 {%0,%1,%2,%3}, [%4];"
                 : "=r"(r0), "=r"(r1), "=r"(r2), "=r"(r3) : "r"(a));
}
__device__ __forceinline__ void mma_bf16(float* d, const u32* a, u32 b0, u32 b1) {
    asm volatile(
        "mma.sync.aligned.m16n8k16.row.col.f32.bf16.bf16.f32 "
        "{%0,%1,%2,%3}, {%4,%5,%6,%7}, {%8,%9}, {%0,%1,%2,%3};"
        : "+f"(d[0]), "+f"(d[1]), "+f"(d[2]), "+f"(d[3])
        : "r"(a[0]), "r"(a[1]), "r"(a[2]), "r"(a[3]), "r"(b0), "r"(b1));
}
__device__ __forceinline__ u32 packbf(__nv_bfloat16 a, __nv_bfloat16 b) {
    return (u32)__bfloat16_as_ushort(a) | ((u32)__bfloat16_as_ushort(b) << 16);
}

// Block 128(M) x 256(N) x 32(K); 256 threads, 8 warps in 2(M) x 4(N), warp 64x64.
// wavefront/mma ratio = 1.0 (vs 1.5 at 64x32) -> smem ceiling ~64% tensor.
// 3-stage cp.async pipeline, 24KB/stage = 72KB dynamic smem.
// Per stage: issue all 16 ldmatrix FIRST, then gmem prefetch, then 64 mma
// (frag latency hidden behind LSU issue + mma stream).
#define STAGE_B 24576u
#define NSTAGE  3
#define SMEM_DYN (NSTAGE * 24576)

__device__ __forceinline__ u32 swadr(u32 base, int row, u32 ch) {
    return base + (u32)row * 64u + ((ch ^ ((u32)(row >> 1) & 3u)) << 4);
}

__device__ __forceinline__ void load_stage(
    u32 sb, int s, const __nv_bfloat16* __restrict__ Ap,
    const __nv_bfloat16* __restrict__ Bp,
    int aRow0, int bRow0, int K, int ko, int tid)
{
    const u32 sA = sb + (u32)s * STAGE_B, sB = sA + 8192u;
#pragma unroll
    for (int it = 0; it < 2; it++) {                // A: 128 rows x 4 chunks
        int slot = tid + it * 256, r = slot >> 2;
        u32 ch = (u32)(slot & 3);
        cp16(swadr(sA, r, ch), Ap + (size_t)(aRow0 + r) * K + ko + (slot & 3) * 8);
    }
#pragma unroll
    for (int it = 0; it < 4; it++) {                // B: 256 rows x 4 chunks
        int slot = tid + it * 256, r = slot >> 2;
        u32 ch = (u32)(slot & 3);
        cp16(swadr(sB, r, ch), Bp + (size_t)(bRow0 + r) * K + ko + (slot & 3) * 8);
    }
}

// 3-pass hi/lo split GEMM mainloop; acc[32][4] = [mi*8+n8][frag]
__device__ __forceinline__ void run_gemm(
    float (*acc)[4], char* smem,
    const __nv_bfloat16* __restrict__ Ahi, const __nv_bfloat16* __restrict__ Alo,
    const __nv_bfloat16* __restrict__ Bhi, const __nv_bfloat16* __restrict__ Blo,
    int aRow0, int bRow0, int K, int kc)
{
    const int tid = threadIdx.x, lane = tid & 31, wid = tid >> 5;
    const int wm = (wid & 1) * 64, wn = (wid >> 1) * 64;
    const u32 sb = smem_u32(smem);
    const int NC = 3 * kc;
    const int lr = lane & 15, lh = lane >> 4;

    // prologue: stages 0..NSTAGE-2
#pragma unroll
    for (int s = 0; s < NSTAGE - 1; ++s) {
        const int pass = s / kc, kk = s - pass * kc;
        const __nv_bfloat16* Ap = (pass < 2) ? Ahi : Alo;
        const __nv_bfloat16* Bp = (pass == 1) ? Blo : Bhi;
        load_stage(sb, s, Ap, Bp, aRow0, bRow0, K, kk * 32, tid);
        cp_commit();
    }

    for (int c = 0; c < NC; ++c) {
        cp_wait<NSTAGE - 2>();
        __syncthreads();                 // stage c resident; stage c-1 consumed

        const u32 sA = sb + (u32)(c % NSTAGE) * STAGE_B, sB = sA + 8192u;

        // 1) issue ALL fragment loads for both k16 halves
        u32 af[2][4][4], bfv[2][4][4];
#pragma unroll
        for (int k16 = 0; k16 < 2; ++k16) {
            const u32 ch = (u32)(k16 * 2 + lh);
#pragma unroll
            for (int mi = 0; mi < 4; ++mi)
                ldm4(swadr(sA, wm + mi * 16 + lr, ch),
                     af[k16][mi][0], af[k16][mi][1], af[k16][mi][2], af[k16][mi][3]);
#pragma unroll
            for (int ni = 0; ni < 4; ++ni)
                ldm4(swadr(sB, wn + ni * 16 + lr, ch),
                     bfv[k16][ni][0], bfv[k16][ni][1], bfv[k16][ni][2], bfv[k16][ni][3]);
        }

        // 2) gmem prefetch for stage c+2 (LSU issue covers ldmatrix latency)
        const int cn = c + NSTAGE - 1;
        if (cn < NC) {
            const int pass = cn / kc, kk = cn - pass * kc;
            const __nv_bfloat16* Ap = (pass < 2) ? Ahi : Alo;
            const __nv_bfloat16* Bp = (pass == 1) ? Blo : Bhi;
            load_stage(sb, cn % NSTAGE, Ap, Bp, aRow0, bRow0, K, kk * 32, tid);
            cp_commit();
        }

        // 3) 64 mma
#pragma unroll
        for (int k16 = 0; k16 < 2; ++k16)
#pragma unroll
            for (int mi = 0; mi < 4; ++mi)
#pragma unroll
                for (int n8 = 0; n8 < 8; ++n8)
                    mma_bf16(acc[mi * 8 + n8], af[k16][mi],
                             bfv[k16][n8 >> 1][n8 & 1], bfv[k16][n8 >> 1][(n8 & 1) + 2]);

        if (cn >= NC) cp_wait<0>();
    }
    __syncthreads();                     // smem safe for epilogue reuse
}

// ============================================================================
// GEMM1: P = h @ W^T  -> store bf16 hi/lo split of P
// ============================================================================
__global__ __launch_bounds__(256, 1) void k_proj() {
    extern __shared__ __align__(1024) char smem[];
    float acc[32][4];
#pragma unroll
    for (int i = 0; i < 32; i++)
#pragma unroll
        for (int j = 0; j < 4; j++) acc[i][j] = 0.f;

    const int rowBase = blockIdx.y * 128, colBase = blockIdx.x * 256;
    run_gemm(acc, smem, g_hHi, g_hLo, g_wHi, g_wLo, rowBase, colBase, DHID, DHID / 32);

    const int lane = threadIdx.x & 31, wid = threadIdx.x >> 5;
    const int wm = (wid & 1) * 64, wn = (wid >> 1) * 64;
#pragma unroll
    for (int mi = 0; mi < 4; ++mi)
#pragma unroll
        for (int mh = 0; mh < 2; ++mh) {
            const int rg = rowBase + wm + mi * 16 + (lane >> 2) + mh * 8;
#pragma unroll
            for (int n8 = 0; n8 < 8; ++n8) {
                const int cg = colBase + wn + n8 * 8 + (lane & 3) * 2;
                float f0 = acc[mi * 8 + n8][mh * 2 + 0];
                float f1 = acc[mi * 8 + n8][mh * 2 + 1];
                __nv_bfloat16 h0 = __float2bfloat16_rn(f0), h1 = __float2bfloat16_rn(f1);
                __nv_bfloat16 l0 = __float2bfloat16_rn(f0 - __bfloat162float(h0));
                __nv_bfloat16 l1 = __float2bfloat16_rn(f1 - __bfloat162float(h1));
                *(u32*)(g_Phi + (size_t)rg * RDIM + cg) = packbf(h0, h1);
                *(u32*)(g_Plo + (size_t)rg * RDIM + cg) = packbf(l0, l1);
            }
        }
}

// ============================================================================
// GEMM2: sim = (wz.wc)*invz*invc fused with softmax statistics
// ============================================================================
__global__ __launch_bounds__(256, 1) void k_sim() {
    extern __shared__ __align__(1024) char smem[];
    float acc[32][4];
#pragma unroll
    for (int i = 0; i < 32; i++)
#pragma unroll
        for (int j = 0; j < 4; j++) acc[i][j] = 0.f;

    const int rowBase = blockIdx.y * 128, colBase = blockIdx.x * 256;
    run_gemm(acc, smem, g_Phi, g_Plo, g_Phi, g_Plo,
             rowBase, BHALF + colBase, RDIM, RDIM / 32);

    const int tid = threadIdx.x, lane = tid & 31, wid = tid >> 5;
    const int wm = (wid & 1) * 64, wn = (wid >> 1) * 64;

    float* invc = (float*)smem;
    invc[tid] = g_invn[BHALF + colBase + tid];
    __syncthreads();

    float vc[16];
#pragma unroll
    for (int n8 = 0; n8 < 8; ++n8) {
        vc[n8 * 2 + 0] = invc[wn + n8 * 8 + (lane & 3) * 2 + 0];
        vc[n8 * 2 + 1] = invc[wn + n8 * 8 + (lane & 3) * 2 + 1];
    }

#pragma unroll
    for (int mi = 0; mi < 4; ++mi)
#pragma unroll
        for (int mh = 0; mh < 2; ++mh) {
            const int rg = rowBase + wm + mi * 16 + (lane >> 2) + mh * 8;
            const float invz = g_invn[rg];
            float se = 0.f, ss = 0.f;
#pragma unroll
            for (int n8 = 0; n8 < 8; ++n8)
#pragma unroll
                for (int q = 0; q < 2; ++q) {
                    const int cl = wn + n8 * 8 + (lane & 3) * 2 + q;
                    float sim = acc[mi * 8 + n8][mh * 2 + q] * invz * vc[n8 * 2 + q];
                    ss += sim;
                    se += __expf(sim - SHIFTC);
                    if (colBase + cl == rg) g_diag[rg] = sim;
                }
            se += __shfl_xor_sync(0xffffffffu, se, 1);
            se += __shfl_xor_sync(0xffffffffu, se, 2);
            ss += __shfl_xor_sync(0xffffffffu, ss, 1);
            ss += __shfl_xor_sync(0xffffffffu, ss, 2);
            if ((lane & 3) == 0) {
                atomicAdd(&g_sumexp[rg], se);
                atomicAdd(&g_rowsum[rg], ss);
            }
        }
}

// ============================================================================
// fp32 -> (bf16 hi, bf16 lo) split conversions
// ============================================================================
__device__ __forceinline__ void split4(float4 v, uint2& hp, uint2& lp) {
    __nv_bfloat16 h0 = __float2bfloat16_rn(v.x), h1 = __float2bfloat16_rn(v.y);
    __nv_bfloat16 h2 = __float2bfloat16_rn(v.z), h3 = __float2bfloat16_rn(v.w);
    __nv_bfloat16 l0 = __float2bfloat16_rn(v.x - __bfloat162float(h0));
    __nv_bfloat16 l1 = __float2bfloat16_rn(v.y - __bfloat162float(h1));
    __nv_bfloat16 l2 = __float2bfloat16_rn(v.z - __bfloat162float(h2));
    __nv_bfloat16 l3 = __float2bfloat16_rn(v.w - __bfloat162float(h3));
    hp.x = packbf(h0, h1); hp.y = packbf(h2, h3);
    lp.x = packbf(l0, l1); lp.y = packbf(l2, l3);
}
__global__ void conv_h(const float4* __restrict__ src) {
    size_t i = (size_t)blockIdx.x * blockDim.x + threadIdx.x;
    uint2 hp, lp;
    split4(src[i], hp, lp);
    ((uint2*)g_hHi)[i] = hp;
    ((uint2*)g_hLo)[i] = lp;
}
__global__ void conv_w(const float4* __restrict__ src) {
    size_t i = (size_t)blockIdx.x * blockDim.x + threadIdx.x;
    uint2 hp, lp;
    split4(src[i], hp, lp);
    ((uint2*)g_wHi)[i] = hp;
    ((uint2*)g_wLo)[i] = lp;
}

// ============================================================================
// Row norms from Phi+Plo; anchor half pre-scaled by 1/TEMP = 10.
// ============================================================================
__device__ __forceinline__ float bfsum2(u32 uh, u32 ul) {
    float a = __bfloat162float(__ushort_as_bfloat16((unsigned short)(uh & 0xFFFF)))
            + __bfloat162float(__ushort_as_bfloat16((unsigned short)(ul & 0xFFFF)));
    float b = __bfloat162float(__ushort_as_bfloat16((unsigned short)(uh >> 16)))
            + __bfloat162float(__ushort_as_bfloat16((unsigned short)(ul >> 16)));
    return a * a + b * b;
}
__global__ void rownorm() {
    const int row = blockIdx.x * 8 + (threadIdx.x >> 5);
    const int lane = threadIdx.x & 31;
    const uint4* ph = (const uint4*)(g_Phi + (size_t)row * RDIM);
    const uint4* pl = (const uint4*)(g_Plo + (size_t)row * RDIM);
    float ss = 0.f;
#pragma unroll
    for (int i = 0; i < 2; i++) {
        uint4 vh = ph[i * 32 + lane];
        uint4 vl = pl[i * 32 + lane];
        ss += bfsum2(vh.x, vl.x) + bfsum2(vh.y, vl.y) + bfsum2(vh.z, vl.z) + bfsum2(vh.w, vl.w);
    }
#pragma unroll
    for (int off = 16; off; off >>= 1) ss += __shfl_xor_sync(0xffffffffu, ss, off);
    if (lane == 0) {
        float inv = 1.0f / sqrtf(ss);
        g_invn[row] = (row < BHALF) ? inv * 10.0f : inv;
    }
}

__global__ void zero_acc() {
    int i = blockIdx.x * blockDim.x + threadIdx.x;
    if (i < BHALF) { g_sumexp[i] = 0.f; g_rowsum[i] = 0.f; }
}

// ============================================================================
// Finalize: [loss, sim_pos, sim_mean] via double-precision reduction.
// ============================================================================
__global__ void finalize(float* __restrict__ out) {
    const int tid = threadIdx.x;
    double l = 0.0, dd = 0.0, rr = 0.0;
    for (int i = tid; i < BHALF; i += 256) {
        float dg = g_diag[i];
        double lse = log((double)g_sumexp[i]) + (double)SHIFTC;
        l += lse - (double)dg;
        dd += (double)dg;
        rr += (double)g_rowsum[i];
    }
    __shared__ double s[256 * 3];
    s[tid] = l; s[tid + 256] = dd; s[tid + 512] = rr;
    __syncthreads();
    for (int st = 128; st; st >>= 1) {
        if (tid < st) {
            s[tid] += s[tid + st];
            s[tid + 256] += s[tid + 256 + st];
            s[tid + 512] += s[tid + 512 + st];
        }
        __syncthreads();
    }
    if (tid == 0) {
        out[0] = (float)(s[0] / (double)BHALF);
        out[1] = (float)(s[256] / (double)BHALF);
        out[2] = (float)(s[512] / ((double)BHALF * (double)BHALF));
    }
}

// ============================================================================
extern "C" void kernel_launch(void* const* d_in, const int* in_sizes, int n_in,
                              void* d_out, int out_size) {
    const float* h = (const float*)d_in[0];
    const float* W = (const float*)d_in[1];
    if (n_in >= 2 && in_sizes[0] == RDIM * DHID && in_sizes[1] == BTOT * DHID) {
        const float* t = h; h = W; W = t;
    }
    float* out = (float*)d_out;

    cudaFuncSetAttribute(k_proj, cudaFuncAttributeMaxDynamicSharedMemorySize, SMEM_DYN);
    cudaFuncSetAttribute(k_sim,  cudaFuncAttributeMaxDynamicSharedMemorySize, SMEM_DYN);

    conv_h<<<(BTOT * DHID / 4) / 256, 256>>>((const float4*)h);
    conv_w<<<(RDIM * DHID / 4) / 256, 256>>>((const float4*)W);
    zero_acc<<<BHALF / 256, 256>>>();
    k_proj<<<dim3(RDIM / 256, BTOT / 128), 256, SMEM_DYN>>>();
    rownorm<<<BTOT / 8, 256>>>();
    k_sim<<<dim3(BHALF / 256, BHALF / 128), 256, SMEM_DYN>>>();
    finalize<<<1, 256>>>(out);
}

// round 17
// speedup vs baseline: 1.2470x; 1.2470x over previous
#include <cuda_runtime.h>
#include <cuda_bf16.h>
#include <math.h>

#define BTOT  16384
#define DHID  2048
#define RDIM  512
#define BHALF 8192
#define SHIFTC 10.0f

typedef unsigned int u32;

// ---------------- scratch (static device globals; no allocs) ----------------
__device__ __align__(16) __nv_bfloat16 g_hHi[(size_t)BTOT * DHID];
__device__ __align__(16) __nv_bfloat16 g_hLo[(size_t)BTOT * DHID];
__device__ __align__(16) __nv_bfloat16 g_wHi[(size_t)RDIM * DHID];
__device__ __align__(16) __nv_bfloat16 g_wLo[(size_t)RDIM * DHID];
__device__ __align__(16) __nv_bfloat16 g_Phi[(size_t)BTOT * RDIM];
__device__ __align__(16) __nv_bfloat16 g_Plo[(size_t)BTOT * RDIM];
__device__ float g_invn[BTOT];
__device__ float g_sumexp[BHALF];
__device__ float g_rowsum[BHALF];
__device__ float g_diag[BHALF];

// ---------------- baseline-PTX helpers ----------------
__device__ __forceinline__ u32 smem_u32(const void* p) {
    u32 a;
    asm("{ .reg .u64 t; cvta.to.shared.u64 t, %1; cvt.u32.u64 %0, t; }" : "=r"(a) : "l"(p));
    return a;
}
__device__ __forceinline__ void cp16(u32 dst, const void* src) {
    asm volatile("cp.async.cg.shared.global [%0], [%1], 16;" :: "r"(dst), "l"(src));
}
__device__ __forceinline__ void cp_commit() {
    asm volatile("cp.async.commit_group;" ::: "memory");
}
template <int N> __device__ __forceinline__ void cp_wait() {
    asm volatile("cp.async.wait_group %0;" :: "n"(N) : "memory");
}
__device__ __forceinline__ void ldm4(u32 a, u32& r0, u32& r1, u32& r2, u32& r3) {
    asm volatile("ldmatrix.sync.aligned.m8n8.x4.shared.b16 {%0,%1,%2,%3}, [%4];"
                 : "=r"(r0), "=r"(r1), "=r"(r2), "=r"(r3) : "r"(a));
}
__device__ __forceinline__ void mma_bf16(float* d, const u32* a, u32 b0, u32 b1) {
    asm volatile(
        "mma.sync.aligned.m16n8k16.row.col.f32.bf16.bf16.f32 "
        "{%0,%1,%2,%3}, {%4,%5,%6,%7}, {%8,%9}, {%0,%1,%2,%3};"
        : "+f"(d[0]), "+f"(d[1]), "+f"(d[2]), "+f"(d[3])
        : "r"(a[0]), "r"(a[1]), "r"(a[2]), "r"(a[3]), "r"(b0), "r"(b1));
}
__device__ __forceinline__ u32 packbf(__nv_bfloat16 a, __nv_bfloat16 b) {
    return (u32)__bfloat16_as_ushort(a) | ((u32)__bfloat16_as_ushort(b) << 16);
}

// Block 128(M) x 256(N) x 32(K); 512 threads, 16 warps in 2(M) x 8(N), warp 64x32.
// FUSED 3-pass: per k-chunk load Ahi|Alo|Bhi|Blo once (48KB stage), issue
// hi*hi + hi*lo + lo*hi mma groups. 2-stage double buffer = 96KB dynamic smem.
// Swizzle: 64B rows, 16B chunk col c' = c ^ ((row>>1)&3) -> conflict-free ldmatrix.
#define STAGE_B 49152u
#define SMEM_DYN (2 * 49152)
#define OFF_ALO  8192u
#define OFF_BHI  16384u
#define OFF_BLO  32768u

__device__ __forceinline__ u32 swadr(u32 base, int row, u32 ch) {
    return base + (u32)row * 64u + ((ch ^ ((u32)(row >> 1) & 3u)) << 4);
}

__device__ __forceinline__ void load_stage(
    u32 sb, int s,
    const __nv_bfloat16* __restrict__ Ahi, const __nv_bfloat16* __restrict__ Alo,
    const __nv_bfloat16* __restrict__ Bhi, const __nv_bfloat16* __restrict__ Blo,
    int aRow0, int bRow0, int K, int ko, int tid)
{
    const u32 ss = sb + (u32)s * STAGE_B;
    const u32 ch = (u32)(tid & 3);
    const int rA = tid >> 2;                        // 0..127
    const size_t aoff = (size_t)(aRow0 + rA) * K + ko + (tid & 3) * 8;
    cp16(swadr(ss, rA, ch), Ahi + aoff);
    cp16(swadr(ss + OFF_ALO, rA, ch), Alo + aoff);
#pragma unroll
    for (int it = 0; it < 2; it++) {                // B: 256 rows
        int slot = tid + it * 512, rB = slot >> 2;
        u32 chb = (u32)(slot & 3);
        const size_t boff = (size_t)(bRow0 + rB) * K + ko + (slot & 3) * 8;
        cp16(swadr(ss + OFF_BHI, rB, chb), Bhi + boff);
        cp16(swadr(ss + OFF_BLO, rB, chb), Blo + boff);
    }
}

// fused hi/lo split GEMM mainloop; acc[16][4] = [mi*4+n8][frag]
__device__ __forceinline__ void run_gemm(
    float (*acc)[4], char* smem,
    const __nv_bfloat16* __restrict__ Ahi, const __nv_bfloat16* __restrict__ Alo,
    const __nv_bfloat16* __restrict__ Bhi, const __nv_bfloat16* __restrict__ Blo,
    int aRow0, int bRow0, int K, int NC)
{
    const int tid = threadIdx.x, lane = tid & 31, wid = tid >> 5;
    const int wm = (wid & 1) * 64, wn = (wid >> 1) * 32;
    const u32 sb = smem_u32(smem);
    const int lr = lane & 15, lh = lane >> 4;

    load_stage(sb, 0, Ahi, Alo, Bhi, Blo, aRow0, bRow0, K, 0, tid);
    cp_commit();

    for (int c = 0; c < NC; ++c) {
        cp_wait<0>();
        __syncthreads();                 // chunk c resident; stage c-1 consumed

        if (c + 1 < NC) {
            load_stage(sb, (c + 1) & 1, Ahi, Alo, Bhi, Blo,
                       aRow0, bRow0, K, (c + 1) * 32, tid);
            cp_commit();
        }

        const u32 ss = sb + (u32)(c & 1) * STAGE_B;
#pragma unroll
        for (int k16 = 0; k16 < 2; ++k16) {
            const u32 ch = (u32)(k16 * 2 + lh);
            u32 ah[4][4], bh[2][4];
#pragma unroll
            for (int mi = 0; mi < 4; ++mi)
                ldm4(swadr(ss, wm + mi * 16 + lr, ch),
                     ah[mi][0], ah[mi][1], ah[mi][2], ah[mi][3]);
#pragma unroll
            for (int ni = 0; ni < 2; ++ni)
                ldm4(swadr(ss + OFF_BHI, wn + ni * 16 + lr, ch),
                     bh[ni][0], bh[ni][1], bh[ni][2], bh[ni][3]);
            // hi * hi
#pragma unroll
            for (int mi = 0; mi < 4; ++mi)
#pragma unroll
                for (int n8 = 0; n8 < 4; ++n8)
                    mma_bf16(acc[mi * 4 + n8], ah[mi],
                             bh[n8 >> 1][n8 & 1], bh[n8 >> 1][(n8 & 1) + 2]);
            // hi * lo
            {
                u32 bl[2][4];
#pragma unroll
                for (int ni = 0; ni < 2; ++ni)
                    ldm4(swadr(ss + OFF_BLO, wn + ni * 16 + lr, ch),
                         bl[ni][0], bl[ni][1], bl[ni][2], bl[ni][3]);
#pragma unroll
                for (int mi = 0; mi < 4; ++mi)
#pragma unroll
                    for (int n8 = 0; n8 < 4; ++n8)
                        mma_bf16(acc[mi * 4 + n8], ah[mi],
                                 bl[n8 >> 1][n8 & 1], bl[n8 >> 1][(n8 & 1) + 2]);
            }
            // lo * hi
            {
                u32 al[4][4];
#pragma unroll
                for (int mi = 0; mi < 4; ++mi)
                    ldm4(swadr(ss + OFF_ALO, wm + mi * 16 + lr, ch),
                         al[mi][0], al[mi][1], al[mi][2], al[mi][3]);
#pragma unroll
                for (int mi = 0; mi < 4; ++mi)
#pragma unroll
                    for (int n8 = 0; n8 < 4; ++n8)
                        mma_bf16(acc[mi * 4 + n8], al[mi],
                                 bh[n8 >> 1][n8 & 1], bh[n8 >> 1][(n8 & 1) + 2]);
            }
        }
    }
    __syncthreads();                     // smem safe for epilogue reuse
}

// ============================================================================
// GEMM1: P = h @ W^T  -> store bf16 hi/lo split of P
// ============================================================================
__global__ __launch_bounds__(512, 1) void k_proj() {
    extern __shared__ __align__(1024) char smem[];
    float acc[16][4];
#pragma unroll
    for (int i = 0; i < 16; i++)
#pragma unroll
        for (int j = 0; j < 4; j++) acc[i][j] = 0.f;

    const int rowBase = blockIdx.y * 128, colBase = blockIdx.x * 256;
    run_gemm(acc, smem, g_hHi, g_hLo, g_wHi, g_wLo,
             rowBase, colBase, DHID, DHID / 32);

    const int lane = threadIdx.x & 31, wid = threadIdx.x >> 5;
    const int wm = (wid & 1) * 64, wn = (wid >> 1) * 32;
#pragma unroll
    for (int mi = 0; mi < 4; ++mi)
#pragma unroll
        for (int mh = 0; mh < 2; ++mh) {
            const int rg = rowBase + wm + mi * 16 + (lane >> 2) + mh * 8;
#pragma unroll
            for (int n8 = 0; n8 < 4; ++n8) {
                const int cg = colBase + wn + n8 * 8 + (lane & 3) * 2;
                float f0 = acc[mi * 4 + n8][mh * 2 + 0];
                float f1 = acc[mi * 4 + n8][mh * 2 + 1];
                __nv_bfloat16 h0 = __float2bfloat16_rn(f0), h1 = __float2bfloat16_rn(f1);
                __nv_bfloat16 l0 = __float2bfloat16_rn(f0 - __bfloat162float(h0));
                __nv_bfloat16 l1 = __float2bfloat16_rn(f1 - __bfloat162float(h1));
                *(u32*)(g_Phi + (size_t)rg * RDIM + cg) = packbf(h0, h1);
                *(u32*)(g_Plo + (size_t)rg * RDIM + cg) = packbf(l0, l1);
            }
        }
}

// ============================================================================
// GEMM2: sim = (wz.wc)*invz*invc fused with softmax statistics
// ============================================================================
__global__ __launch_bounds__(512, 1) void k_sim() {
    extern __shared__ __align__(1024) char smem[];
    float acc[16][4];
#pragma unroll
    for (int i = 0; i < 16; i++)
#pragma unroll
        for (int j = 0; j < 4; j++) acc[i][j] = 0.f;

    const int rowBase = blockIdx.y * 128, colBase = blockIdx.x * 256;
    run_gemm(acc, smem, g_Phi, g_Plo, g_Phi, g_Plo,
             rowBase, BHALF + colBase, RDIM, RDIM / 32);

    const int tid = threadIdx.x, lane = tid & 31, wid = tid >> 5;
    const int wm = (wid & 1) * 64, wn = (wid >> 1) * 32;

    float* invc = (float*)smem;
    if (tid < 256) invc[tid] = g_invn[BHALF + colBase + tid];
    __syncthreads();

    float vc[8];
#pragma unroll
    for (int n8 = 0; n8 < 4; ++n8) {
        vc[n8 * 2 + 0] = invc[wn + n8 * 8 + (lane & 3) * 2 + 0];
        vc[n8 * 2 + 1] = invc[wn + n8 * 8 + (lane & 3) * 2 + 1];
    }

#pragma unroll
    for (int mi = 0; mi < 4; ++mi)
#pragma unroll
        for (int mh = 0; mh < 2; ++mh) {
            const int rg = rowBase + wm + mi * 16 + (lane >> 2) + mh * 8;
            const float invz = g_invn[rg];
            float se = 0.f, ss = 0.f;
#pragma unroll
            for (int n8 = 0; n8 < 4; ++n8)
#pragma unroll
                for (int q = 0; q < 2; ++q) {
                    const int cl = wn + n8 * 8 + (lane & 3) * 2 + q;
                    float sim = acc[mi * 4 + n8][mh * 2 + q] * invz * vc[n8 * 2 + q];
                    ss += sim;
                    se += __expf(sim - SHIFTC);
                    if (colBase + cl == rg) g_diag[rg] = sim;
                }
            se += __shfl_xor_sync(0xffffffffu, se, 1);
            se += __shfl_xor_sync(0xffffffffu, se, 2);
            ss += __shfl_xor_sync(0xffffffffu, ss, 1);
            ss += __shfl_xor_sync(0xffffffffu, ss, 2);
            if ((lane & 3) == 0) {
                atomicAdd(&g_sumexp[rg], se);
                atomicAdd(&g_rowsum[rg], ss);
            }
        }
}

// ============================================================================
// fp32 -> (bf16 hi, bf16 lo) split conversions
// ============================================================================
__device__ __forceinline__ void split4(float4 v, uint2& hp, uint2& lp) {
    __nv_bfloat16 h0 = __float2bfloat16_rn(v.x), h1 = __float2bfloat16_rn(v.y);
    __nv_bfloat16 h2 = __float2bfloat16_rn(v.z), h3 = __float2bfloat16_rn(v.w);
    __nv_bfloat16 l0 = __float2bfloat16_rn(v.x - __bfloat162float(h0));
    __nv_bfloat16 l1 = __float2bfloat16_rn(v.y - __bfloat162float(h1));
    __nv_bfloat16 l2 = __float2bfloat16_rn(v.z - __bfloat162float(h2));
    __nv_bfloat16 l3 = __float2bfloat16_rn(v.w - __bfloat162float(h3));
    hp.x = packbf(h0, h1); hp.y = packbf(h2, h3);
    lp.x = packbf(l0, l1); lp.y = packbf(l2, l3);
}
__global__ void conv_h(const float4* __restrict__ src) {
    size_t i = (size_t)blockIdx.x * blockDim.x + threadIdx.x;
    uint2 hp, lp;
    split4(src[i], hp, lp);
    ((uint2*)g_hHi)[i] = hp;
    ((uint2*)g_hLo)[i] = lp;
}
__global__ void conv_w(const float4* __restrict__ src) {
    size_t i = (size_t)blockIdx.x * blockDim.x + threadIdx.x;
    uint2 hp, lp;
    split4(src[i], hp, lp);
    ((uint2*)g_wHi)[i] = hp;
    ((uint2*)g_wLo)[i] = lp;
}

// ============================================================================
// Row norms from Phi+Plo; anchor half pre-scaled by 1/TEMP = 10.
// ============================================================================
__device__ __forceinline__ float bfsum2(u32 uh, u32 ul) {
    float a = __bfloat162float(__ushort_as_bfloat16((unsigned short)(uh & 0xFFFF)))
            + __bfloat162float(__ushort_as_bfloat16((unsigned short)(ul & 0xFFFF)));
    float b = __bfloat162float(__ushort_as_bfloat16((unsigned short)(uh >> 16)))
            + __bfloat162float(__ushort_as_bfloat16((unsigned short)(ul >> 16)));
    return a * a + b * b;
}
__global__ void rownorm() {
    const int row = blockIdx.x * 8 + (threadIdx.x >> 5);
    const int lane = threadIdx.x & 31;
    const uint4* ph = (const uint4*)(g_Phi + (size_t)row * RDIM);
    const uint4* pl = (const uint4*)(g_Plo + (size_t)row * RDIM);
    float ss = 0.f;
#pragma unroll
    for (int i = 0; i < 2; i++) {
        uint4 vh = ph[i * 32 + lane];
        uint4 vl = pl[i * 32 + lane];
        ss += bfsum2(vh.x, vl.x) + bfsum2(vh.y, vl.y) + bfsum2(vh.z, vl.z) + bfsum2(vh.w, vl.w);
    }
#pragma unroll
    for (int off = 16; off; off >>= 1) ss += __shfl_xor_sync(0xffffffffu, ss, off);
    if (lane == 0) {
        float inv = 1.0f / sqrtf(ss);
        g_invn[row] = (row < BHALF) ? inv * 10.0f : inv;
    }
}

__global__ void zero_acc() {
    int i = blockIdx.x * blockDim.x + threadIdx.x;
    if (i < BHALF) { g_sumexp[i] = 0.f; g_rowsum[i] = 0.f; }
}

// ============================================================================
// Finalize: [loss, sim_pos, sim_mean] via double-precision reduction.
// ============================================================================
__global__ void finalize(float* __restrict__ out) {
    const int tid = threadIdx.x;
    double l = 0.0, dd = 0.0, rr = 0.0;
    for (int i = tid; i < BHALF; i += 256) {
        float dg = g_diag[i];
        double lse = log((double)g_sumexp[i]) + (double)SHIFTC;
        l += lse - (double)dg;
        dd += (double)dg;
        rr += (double)g_rowsum[i];
    }
    __shared__ double s[256 * 3];
    s[tid] = l; s[tid + 256] = dd; s[tid + 512] = rr;
    __syncthreads();
    for (int st = 128; st; st >>= 1) {
        if (tid < st) {
            s[tid] += s[tid + st];
            s[tid + 256] += s[tid + 256 + st];
            s[tid + 512] += s[tid + 512 + st];
        }
        __syncthreads();
    }
    if (tid == 0) {
        out[0] = (float)(s[0] / (double)BHALF);
        out[1] = (float)(s[256] / (double)BHALF);
        out[2] = (float)(s[512] / ((double)BHALF * (double)BHALF));
    }
}

// ============================================================================
extern "C" void kernel_launch(void* const* d_in, const int* in_sizes, int n_in,
                              void* d_out, int out_size) {
    const float* h = (const float*)d_in[0];
    const float* W = (const float*)d_in[1];
    if (n_in >= 2 && in_sizes[0] == RDIM * DHID && in_sizes[1] == BTOT * DHID) {
        const float* t = h; h = W; W = t;
    }
    float* out = (float*)d_out;

    cudaFuncSetAttribute(k_proj, cudaFuncAttributeMaxDynamicSharedMemorySize, SMEM_DYN);
    cudaFuncSetAttribute(k_sim,  cudaFuncAttributeMaxDynamicSharedMemorySize, SMEM_DYN);

    conv_h<<<(BTOT * DHID / 4) / 256, 256>>>((const float4*)h);
    conv_w<<<(RDIM * DHID / 4) / 256, 256>>>((const float4*)W);
    zero_acc<<<BHALF / 256, 256>>>();
    k_proj<<<dim3(RDIM / 256, BTOT / 128), 512, SMEM_DYN>>>();
    rownorm<<<BTOT / 8, 256>>>();
    k_sim<<<dim3(BHALF / 256, BHALF / 128), 512, SMEM_DYN>>>();
    finalize<<<1, 256>>>(out);
}